// round 3
// baseline (speedup 1.0000x reference)
#include <cuda_runtime.h>

// ---------------------------------------------------------------------------
// Performer (FAVOR+) linear attention, fully fused, fp32 SIMT baseline.
// One CTA per (b,h). Phase 1: context[m,e] = k'^T v and kcs[m] = colsum(k').
// Phase 2: q' rows -> D_inv -> out = (q' @ context) * D_inv.
// ratio = m^-0.5 cancels through D_inv and is dropped.
// ---------------------------------------------------------------------------

namespace {
constexpr int N_TOK  = 2048;
constexpr int D_DIM  = 64;
constexpr int M_FEAT = 256;
constexpr int NT     = 64;                 // rows per tile
constexpr int NTILES = N_TOK / NT;         // 32
constexpr int THREADS = 512;

constexpr int KPLD  = 260;                 // kp/qp row stride (floats), pad vs bank conflicts
constexpr int KSTLD = 68;                  // Kst/Qst row stride (floats)

// smem layout (float offsets)
constexpr int OFF_P    = 0;                         // Pst[64][256]        16384
constexpr int OFF_KP   = OFF_P   + D_DIM * M_FEAT;  // kp/qp[64][260]      16640
constexpr int OFF_KST  = OFF_KP  + NT * KPLD;       // Kst/Qst[64][68]      4352
constexpr int OFF_X    = OFF_KST + D_DIM * KSTLD;   // Vs[64][64] | ctx[256][64] 16384
constexpr int OFF_KCS  = OFF_X   + M_FEAT * D_DIM;  // kcs[256]
constexpr int OFF_DIAG = OFF_KCS + M_FEAT;          // diag[64]
constexpr int OFF_DINV = OFF_DIAG + NT;             // dinv[64]
constexpr int SMEM_FLOATS = OFF_DINV + NT;          // 54144 floats
constexpr int SMEM_BYTES  = SMEM_FLOATS * 4;        // 216576 bytes

constexpr float NRM  = 0.35355339059327373f;        // 64^-0.25
constexpr float EPSF = 1e-4f;
}

__global__ __launch_bounds__(THREADS, 1)
void fastattn_kernel(const float* __restrict__ qg_,
                     const float* __restrict__ kg_,
                     const float* __restrict__ vg_,
                     const float* __restrict__ Pg,
                     float* __restrict__ outg_)
{
    extern __shared__ float sm[];
    float* Ps   = sm + OFF_P;     // [d][m] transposed projection
    float* kp   = sm + OFF_KP;    // k' / q' tile  [n][KPLD]
    float* Ks   = sm + OFF_KST;   // K/Q tile transposed, pre-scaled  [d][KSTLD]
    float* Vs   = sm + OFF_X;     // V tile [n][64]          (phase 1)
    float* ctx  = sm + OFF_X;     // context [m][64]         (phase 2, aliases Vs)
    float* kcs  = sm + OFF_KCS;   // column sums of k'
    float* diag = sm + OFF_DIAG;
    float* dinv = sm + OFF_DINV;

    const int tid = threadIdx.x;
    const int w   = tid >> 5;     // warp 0..15
    const int c   = tid & 31;     // lane
    const int bh  = blockIdx.x;

    const float* qg = qg_ + (size_t)bh * N_TOK * D_DIM;
    const float* kg = kg_ + (size_t)bh * N_TOK * D_DIM;
    const float* vg = vg_ + (size_t)bh * N_TOK * D_DIM;
    float*       og = outg_ + (size_t)bh * N_TOK * D_DIM;

    // ---- load P transposed into smem (once) ----
    for (int i = tid; i < M_FEAT * D_DIM / 4; i += THREADS) {
        int m  = i >> 4;          // 16 float4 per 64-float row
        int d4 = (i & 15) * 4;
        float4 pv = ((const float4*)Pg)[i];
        Ps[(d4 + 0) * M_FEAT + m] = pv.x;
        Ps[(d4 + 1) * M_FEAT + m] = pv.y;
        Ps[(d4 + 2) * M_FEAT + m] = pv.z;
        Ps[(d4 + 3) * M_FEAT + m] = pv.w;
    }

    // ---- phase 1: context & kcs ----
    float cacc[8][4];             // ctx accumulators: m-set {4c+j, 128+4c+j} x e-set {4w..4w+3}
    #pragma unroll
    for (int j = 0; j < 8; j++)
        #pragma unroll
        for (int e = 0; e < 4; e++) cacc[j][e] = 0.f;
    float kcsr = 0.f;             // threads < 256: column tid of kcs

    for (int t = 0; t < NTILES; t++) {
        const float* kt = kg + t * NT * D_DIM;
        const float* vt = vg + t * NT * D_DIM;
        __syncthreads();          // previous tile fully consumed
        // load K (transpose + scale) and V
        #pragma unroll
        for (int r = 0; r < 2; r++) {
            int i  = tid + r * THREADS;          // 0..1023
            int n  = i >> 4;
            int d4 = (i & 15) * 4;
            float4 kv = ((const float4*)kt)[i];
            Ks[(d4 + 0) * KSTLD + n] = kv.x * NRM;
            Ks[(d4 + 1) * KSTLD + n] = kv.y * NRM;
            Ks[(d4 + 2) * KSTLD + n] = kv.z * NRM;
            Ks[(d4 + 3) * KSTLD + n] = kv.w * NRM;
            ((float4*)Vs)[i] = ((const float4*)vt)[i];
        }
        __syncthreads();
        if (tid < NT) {           // diag[n] = 0.5 * sum_d (scaled)^2
            float s = 0.f;
            #pragma unroll 8
            for (int d = 0; d < D_DIM; d++) { float x = Ks[d * KSTLD + tid]; s += x * x; }
            diag[tid] = 0.5f * s;
        }
        __syncthreads();
        // kdash GEMM (64x256, K=64), fused exp -> kp
        {
            float acc[4][8];
            #pragma unroll
            for (int i = 0; i < 4; i++)
                #pragma unroll
                for (int j = 0; j < 8; j++) acc[i][j] = 0.f;
            const int n0 = w * 4, mA = c * 4, mB = 128 + c * 4;
            #pragma unroll 4
            for (int d = 0; d < D_DIM; d++) {
                float4 a  = *(const float4*)&Ks[d * KSTLD + n0];
                float4 bA = *(const float4*)&Ps[d * M_FEAT + mA];
                float4 bB = *(const float4*)&Ps[d * M_FEAT + mB];
                float av[4] = {a.x, a.y, a.z, a.w};
                float bv[8] = {bA.x, bA.y, bA.z, bA.w, bB.x, bB.y, bB.z, bB.w};
                #pragma unroll
                for (int i = 0; i < 4; i++)
                    #pragma unroll
                    for (int j = 0; j < 8; j++) acc[i][j] += av[i] * bv[j];
            }
            #pragma unroll
            for (int i = 0; i < 4; i++) {
                float dg = diag[n0 + i];
                float4 e0, e1;
                e0.x = __expf(acc[i][0] - dg + EPSF);
                e0.y = __expf(acc[i][1] - dg + EPSF);
                e0.z = __expf(acc[i][2] - dg + EPSF);
                e0.w = __expf(acc[i][3] - dg + EPSF);
                e1.x = __expf(acc[i][4] - dg + EPSF);
                e1.y = __expf(acc[i][5] - dg + EPSF);
                e1.z = __expf(acc[i][6] - dg + EPSF);
                e1.w = __expf(acc[i][7] - dg + EPSF);
                *(float4*)&kp[(n0 + i) * KPLD + mA] = e0;
                *(float4*)&kp[(n0 + i) * KPLD + mB] = e1;
            }
        }
        __syncthreads();
        // kcs partial sums (thread t owns column t)
        if (tid < M_FEAT) {
            float s = 0.f;
            #pragma unroll 8
            for (int n = 0; n < NT; n++) s += kp[n * KPLD + tid];
            kcsr += s;
        }
        // ctx GEMM: ctx[m][e] += kp[n][m] * Vs[n][e]
        {
            const int mA = c * 4, mB = 128 + c * 4, e0 = w * 4;
            #pragma unroll 4
            for (int n = 0; n < NT; n++) {
                float4 pA = *(const float4*)&kp[n * KPLD + mA];
                float4 pB = *(const float4*)&kp[n * KPLD + mB];
                float4 vv = *(const float4*)&Vs[n * D_DIM + e0];
                float pv[8] = {pA.x, pA.y, pA.z, pA.w, pB.x, pB.y, pB.z, pB.w};
                float ev[4] = {vv.x, vv.y, vv.z, vv.w};
                #pragma unroll
                for (int j = 0; j < 8; j++)
                    #pragma unroll
                    for (int e = 0; e < 4; e++) cacc[j][e] += pv[j] * ev[e];
            }
        }
    }
    __syncthreads();              // last tile done; Vs dead -> ctx can be written
    {
        const int mA = c * 4, mB = 128 + c * 4, e0 = w * 4;
        #pragma unroll
        for (int j = 0; j < 4; j++) {
            *(float4*)&ctx[(mA + j) * D_DIM + e0] =
                make_float4(cacc[j][0], cacc[j][1], cacc[j][2], cacc[j][3]);
            *(float4*)&ctx[(mB + j) * D_DIM + e0] =
                make_float4(cacc[4 + j][0], cacc[4 + j][1], cacc[4 + j][2], cacc[4 + j][3]);
        }
        if (tid < M_FEAT) kcs[tid] = kcsr;
    }

    // ---- phase 2: q', D_inv, out ----
    for (int t = 0; t < NTILES; t++) {
        const float* qt = qg + t * NT * D_DIM;
        __syncthreads();          // ctx/kcs visible; previous out GEMM done with qp
        #pragma unroll
        for (int r = 0; r < 2; r++) {
            int i  = tid + r * THREADS;
            int n  = i >> 4;
            int d4 = (i & 15) * 4;
            float4 qv = ((const float4*)qt)[i];
            Ks[(d4 + 0) * KSTLD + n] = qv.x * NRM;
            Ks[(d4 + 1) * KSTLD + n] = qv.y * NRM;
            Ks[(d4 + 2) * KSTLD + n] = qv.z * NRM;
            Ks[(d4 + 3) * KSTLD + n] = qv.w * NRM;
        }
        __syncthreads();
        if (tid < NT) {
            float s = 0.f;
            #pragma unroll 8
            for (int d = 0; d < D_DIM; d++) { float x = Ks[d * KSTLD + tid]; s += x * x; }
            diag[tid] = 0.5f * s;
        }
        __syncthreads();
        // qdash GEMM + rowmax + exp + denom
        {
            float acc[4][8];
            #pragma unroll
            for (int i = 0; i < 4; i++)
                #pragma unroll
                for (int j = 0; j < 8; j++) acc[i][j] = 0.f;
            const int n0 = w * 4, mA = c * 4, mB = 128 + c * 4;
            #pragma unroll 4
            for (int d = 0; d < D_DIM; d++) {
                float4 a  = *(const float4*)&Ks[d * KSTLD + n0];
                float4 bA = *(const float4*)&Ps[d * M_FEAT + mA];
                float4 bB = *(const float4*)&Ps[d * M_FEAT + mB];
                float av[4] = {a.x, a.y, a.z, a.w};
                float bv[8] = {bA.x, bA.y, bA.z, bA.w, bB.x, bB.y, bB.z, bB.w};
                #pragma unroll
                for (int i = 0; i < 4; i++)
                    #pragma unroll
                    for (int j = 0; j < 8; j++) acc[i][j] += av[i] * bv[j];
            }
            float4 kcA = *(const float4*)&kcs[mA];
            float4 kcB = *(const float4*)&kcs[mB];
            float kcv[8] = {kcA.x, kcA.y, kcA.z, kcA.w, kcB.x, kcB.y, kcB.z, kcB.w};
            #pragma unroll
            for (int i = 0; i < 4; i++) {
                float mx = acc[i][0];
                #pragma unroll
                for (int j = 1; j < 8; j++) mx = fmaxf(mx, acc[i][j]);
                #pragma unroll
                for (int off = 16; off; off >>= 1)
                    mx = fmaxf(mx, __shfl_xor_sync(0xffffffffu, mx, off));
                float dg = diag[n0 + i];
                float qpv[8];
                float ds = 0.f;
                #pragma unroll
                for (int j = 0; j < 8; j++) {
                    qpv[j] = __expf(acc[i][j] - dg - mx) + EPSF;   // EPS outside exp for queries
                    ds += qpv[j] * kcv[j];
                }
                *(float4*)&kp[(n0 + i) * KPLD + mA] = make_float4(qpv[0], qpv[1], qpv[2], qpv[3]);
                *(float4*)&kp[(n0 + i) * KPLD + mB] = make_float4(qpv[4], qpv[5], qpv[6], qpv[7]);
                #pragma unroll
                for (int off = 16; off; off >>= 1)
                    ds += __shfl_xor_sync(0xffffffffu, ds, off);
                if (c == 0) dinv[n0 + i] = 1.0f / ds;
            }
        }
        __syncthreads();
        // out GEMM: out[n][e] = dinv[n] * sum_m qp[n][m] * ctx[m][e]
        {
            const int r0 = (tid >> 4) * 2;
            const int e0 = (tid & 15) * 4;
            float o0[4] = {0.f, 0.f, 0.f, 0.f};
            float o1[4] = {0.f, 0.f, 0.f, 0.f};
            #pragma unroll 4
            for (int mc = 0; mc < M_FEAT; mc += 8) {
                float4 qa0 = *(const float4*)&kp[r0 * KPLD + mc];
                float4 qa1 = *(const float4*)&kp[r0 * KPLD + mc + 4];
                float4 qb0 = *(const float4*)&kp[(r0 + 1) * KPLD + mc];
                float4 qb1 = *(const float4*)&kp[(r0 + 1) * KPLD + mc + 4];
                float qa[8] = {qa0.x, qa0.y, qa0.z, qa0.w, qa1.x, qa1.y, qa1.z, qa1.w};
                float qb[8] = {qb0.x, qb0.y, qb0.z, qb0.w, qb1.x, qb1.y, qb1.z, qb1.w};
                #pragma unroll
                for (int j = 0; j < 8; j++) {
                    float4 cv = *(const float4*)&ctx[(mc + j) * D_DIM + e0];
                    o0[0] += qa[j] * cv.x; o0[1] += qa[j] * cv.y;
                    o0[2] += qa[j] * cv.z; o0[3] += qa[j] * cv.w;
                    o1[0] += qb[j] * cv.x; o1[1] += qb[j] * cv.y;
                    o1[2] += qb[j] * cv.z; o1[3] += qb[j] * cv.w;
                }
            }
            float d0 = dinv[r0], d1 = dinv[r0 + 1];
            *(float4*)&og[(t * NT + r0) * D_DIM + e0] =
                make_float4(o0[0] * d0, o0[1] * d0, o0[2] * d0, o0[3] * d0);
            *(float4*)&og[(t * NT + r0 + 1) * D_DIM + e0] =
                make_float4(o1[0] * d1, o1[1] * d1, o1[2] * d1, o1[3] * d1);
        }
    }
}

extern "C" void kernel_launch(void* const* d_in, const int* in_sizes, int n_in,
                              void* d_out, int out_size)
{
    (void)n_in; (void)out_size;
    const float* q = (const float*)d_in[0];
    const float* k = (const float*)d_in[1];
    const float* v = (const float*)d_in[2];
    const float* P = (const float*)d_in[3];
    float* out = (float*)d_out;

    const int bh = in_sizes[0] / (N_TOK * D_DIM);   // 128

    cudaFuncSetAttribute(fastattn_kernel,
                         cudaFuncAttributeMaxDynamicSharedMemorySize, SMEM_BYTES);
    fastattn_kernel<<<bh, THREADS, SMEM_BYTES>>>(q, k, v, P, out);
}

// round 4
// speedup vs baseline: 1.0008x; 1.0008x over previous
#include <cuda_runtime.h>

// ---------------------------------------------------------------------------
// Performer (FAVOR+) linear attention, fully fused, fp32 SIMT baseline.
// One CTA per (b,h). Phase 1: context[m,e] = k'^T v and kcs[m] = colsum(k').
// Phase 2: q' rows -> D_inv -> out = (q' @ context) * D_inv.
// ratio = m^-0.5 cancels through D_inv and is dropped.
// ---------------------------------------------------------------------------

namespace {
constexpr int N_TOK  = 2048;
constexpr int D_DIM  = 64;
constexpr int M_FEAT = 256;
constexpr int NT     = 64;                 // rows per tile
constexpr int NTILES = N_TOK / NT;         // 32
constexpr int THREADS = 512;

constexpr int KPLD  = 260;                 // kp/qp row stride (floats), pad vs bank conflicts
constexpr int KSTLD = 68;                  // Kst/Qst row stride (floats)

// smem layout (float offsets)
constexpr int OFF_P    = 0;                         // Pst[64][256]        16384
constexpr int OFF_KP   = OFF_P   + D_DIM * M_FEAT;  // kp/qp[64][260]      16640
constexpr int OFF_KST  = OFF_KP  + NT * KPLD;       // Kst/Qst[64][68]      4352
constexpr int OFF_X    = OFF_KST + D_DIM * KSTLD;   // Vs[64][64] | ctx[256][64] 16384
constexpr int OFF_KCS  = OFF_X   + M_FEAT * D_DIM;  // kcs[256]
constexpr int OFF_DIAG = OFF_KCS + M_FEAT;          // diag[64]
constexpr int OFF_DINV = OFF_DIAG + NT;             // dinv[64]
constexpr int SMEM_FLOATS = OFF_DINV + NT;          // 54144 floats
constexpr int SMEM_BYTES  = SMEM_FLOATS * 4;        // 216576 bytes

constexpr float NRM  = 0.35355339059327373f;        // 64^-0.25
constexpr float EPSF = 1e-4f;
}

__global__ __launch_bounds__(THREADS, 1)
void fastattn_kernel(const float* __restrict__ qg_,
                     const float* __restrict__ kg_,
                     const float* __restrict__ vg_,
                     const float* __restrict__ Pg,
                     float* __restrict__ outg_)
{
    extern __shared__ float sm[];
    float* Ps   = sm + OFF_P;     // [d][m] transposed projection
    float* kp   = sm + OFF_KP;    // k' / q' tile  [n][KPLD]
    float* Ks   = sm + OFF_KST;   // K/Q tile transposed, pre-scaled  [d][KSTLD]
    float* Vs   = sm + OFF_X;     // V tile [n][64]          (phase 1)
    float* ctx  = sm + OFF_X;     // context [m][64]         (phase 2, aliases Vs)
    float* kcs  = sm + OFF_KCS;   // column sums of k'
    float* diag = sm + OFF_DIAG;
    float* dinv = sm + OFF_DINV;

    const int tid = threadIdx.x;
    const int w   = tid >> 5;     // warp 0..15
    const int c   = tid & 31;     // lane
    const int bh  = blockIdx.x;

    const float* qg = qg_ + (size_t)bh * N_TOK * D_DIM;
    const float* kg = kg_ + (size_t)bh * N_TOK * D_DIM;
    const float* vg = vg_ + (size_t)bh * N_TOK * D_DIM;
    float*       og = outg_ + (size_t)bh * N_TOK * D_DIM;

    // ---- load P transposed into smem (once) ----
    for (int i = tid; i < M_FEAT * D_DIM / 4; i += THREADS) {
        int m  = i >> 4;          // 16 float4 per 64-float row
        int d4 = (i & 15) * 4;
        float4 pv = ((const float4*)Pg)[i];
        Ps[(d4 + 0) * M_FEAT + m] = pv.x;
        Ps[(d4 + 1) * M_FEAT + m] = pv.y;
        Ps[(d4 + 2) * M_FEAT + m] = pv.z;
        Ps[(d4 + 3) * M_FEAT + m] = pv.w;
    }

    // ---- phase 1: context & kcs ----
    float cacc[8][4];             // ctx accumulators: m-set {4c+j, 128+4c+j} x e-set {4w..4w+3}
    #pragma unroll
    for (int j = 0; j < 8; j++)
        #pragma unroll
        for (int e = 0; e < 4; e++) cacc[j][e] = 0.f;
    float kcsr = 0.f;             // threads < 256: column tid of kcs

    for (int t = 0; t < NTILES; t++) {
        const float* kt = kg + t * NT * D_DIM;
        const float* vt = vg + t * NT * D_DIM;
        __syncthreads();          // previous tile fully consumed
        // load K (transpose + scale) and V
        #pragma unroll
        for (int r = 0; r < 2; r++) {
            int i  = tid + r * THREADS;          // 0..1023
            int n  = i >> 4;
            int d4 = (i & 15) * 4;
            float4 kv = ((const float4*)kt)[i];
            Ks[(d4 + 0) * KSTLD + n] = kv.x * NRM;
            Ks[(d4 + 1) * KSTLD + n] = kv.y * NRM;
            Ks[(d4 + 2) * KSTLD + n] = kv.z * NRM;
            Ks[(d4 + 3) * KSTLD + n] = kv.w * NRM;
            ((float4*)Vs)[i] = ((const float4*)vt)[i];
        }
        __syncthreads();
        if (tid < NT) {           // diag[n] = 0.5 * sum_d (scaled)^2
            float s = 0.f;
            #pragma unroll 8
            for (int d = 0; d < D_DIM; d++) { float x = Ks[d * KSTLD + tid]; s += x * x; }
            diag[tid] = 0.5f * s;
        }
        __syncthreads();
        // kdash GEMM (64x256, K=64), fused exp -> kp
        {
            float acc[4][8];
            #pragma unroll
            for (int i = 0; i < 4; i++)
                #pragma unroll
                for (int j = 0; j < 8; j++) acc[i][j] = 0.f;
            const int n0 = w * 4, mA = c * 4, mB = 128 + c * 4;
            #pragma unroll 4
            for (int d = 0; d < D_DIM; d++) {
                float4 a  = *(const float4*)&Ks[d * KSTLD + n0];
                float4 bA = *(const float4*)&Ps[d * M_FEAT + mA];
                float4 bB = *(const float4*)&Ps[d * M_FEAT + mB];
                float av[4] = {a.x, a.y, a.z, a.w};
                float bv[8] = {bA.x, bA.y, bA.z, bA.w, bB.x, bB.y, bB.z, bB.w};
                #pragma unroll
                for (int i = 0; i < 4; i++)
                    #pragma unroll
                    for (int j = 0; j < 8; j++) acc[i][j] += av[i] * bv[j];
            }
            #pragma unroll
            for (int i = 0; i < 4; i++) {
                float dg = diag[n0 + i];
                float4 e0, e1;
                e0.x = __expf(acc[i][0] - dg + EPSF);
                e0.y = __expf(acc[i][1] - dg + EPSF);
                e0.z = __expf(acc[i][2] - dg + EPSF);
                e0.w = __expf(acc[i][3] - dg + EPSF);
                e1.x = __expf(acc[i][4] - dg + EPSF);
                e1.y = __expf(acc[i][5] - dg + EPSF);
                e1.z = __expf(acc[i][6] - dg + EPSF);
                e1.w = __expf(acc[i][7] - dg + EPSF);
                *(float4*)&kp[(n0 + i) * KPLD + mA] = e0;
                *(float4*)&kp[(n0 + i) * KPLD + mB] = e1;
            }
        }
        __syncthreads();
        // kcs partial sums (thread t owns column t)
        if (tid < M_FEAT) {
            float s = 0.f;
            #pragma unroll 8
            for (int n = 0; n < NT; n++) s += kp[n * KPLD + tid];
            kcsr += s;
        }
        // ctx GEMM: ctx[m][e] += kp[n][m] * Vs[n][e]
        {
            const int mA = c * 4, mB = 128 + c * 4, e0 = w * 4;
            #pragma unroll 4
            for (int n = 0; n < NT; n++) {
                float4 pA = *(const float4*)&kp[n * KPLD + mA];
                float4 pB = *(const float4*)&kp[n * KPLD + mB];
                float4 vv = *(const float4*)&Vs[n * D_DIM + e0];
                float pv[8] = {pA.x, pA.y, pA.z, pA.w, pB.x, pB.y, pB.z, pB.w};
                float ev[4] = {vv.x, vv.y, vv.z, vv.w};
                #pragma unroll
                for (int j = 0; j < 8; j++)
                    #pragma unroll
                    for (int e = 0; e < 4; e++) cacc[j][e] += pv[j] * ev[e];
            }
        }
    }
    __syncthreads();              // last tile done; Vs dead -> ctx can be written
    {
        const int mA = c * 4, mB = 128 + c * 4, e0 = w * 4;
        #pragma unroll
        for (int j = 0; j < 4; j++) {
            *(float4*)&ctx[(mA + j) * D_DIM + e0] =
                make_float4(cacc[j][0], cacc[j][1], cacc[j][2], cacc[j][3]);
            *(float4*)&ctx[(mB + j) * D_DIM + e0] =
                make_float4(cacc[4 + j][0], cacc[4 + j][1], cacc[4 + j][2], cacc[4 + j][3]);
        }
        if (tid < M_FEAT) kcs[tid] = kcsr;
    }

    // ---- phase 2: q', D_inv, out ----
    for (int t = 0; t < NTILES; t++) {
        const float* qt = qg + t * NT * D_DIM;
        __syncthreads();          // ctx/kcs visible; previous out GEMM done with qp
        #pragma unroll
        for (int r = 0; r < 2; r++) {
            int i  = tid + r * THREADS;
            int n  = i >> 4;
            int d4 = (i & 15) * 4;
            float4 qv = ((const float4*)qt)[i];
            Ks[(d4 + 0) * KSTLD + n] = qv.x * NRM;
            Ks[(d4 + 1) * KSTLD + n] = qv.y * NRM;
            Ks[(d4 + 2) * KSTLD + n] = qv.z * NRM;
            Ks[(d4 + 3) * KSTLD + n] = qv.w * NRM;
        }
        __syncthreads();
        if (tid < NT) {
            float s = 0.f;
            #pragma unroll 8
            for (int d = 0; d < D_DIM; d++) { float x = Ks[d * KSTLD + tid]; s += x * x; }
            diag[tid] = 0.5f * s;
        }
        __syncthreads();
        // qdash GEMM + rowmax + exp + denom
        {
            float acc[4][8];
            #pragma unroll
            for (int i = 0; i < 4; i++)
                #pragma unroll
                for (int j = 0; j < 8; j++) acc[i][j] = 0.f;
            const int n0 = w * 4, mA = c * 4, mB = 128 + c * 4;
            #pragma unroll 4
            for (int d = 0; d < D_DIM; d++) {
                float4 a  = *(const float4*)&Ks[d * KSTLD + n0];
                float4 bA = *(const float4*)&Ps[d * M_FEAT + mA];
                float4 bB = *(const float4*)&Ps[d * M_FEAT + mB];
                float av[4] = {a.x, a.y, a.z, a.w};
                float bv[8] = {bA.x, bA.y, bA.z, bA.w, bB.x, bB.y, bB.z, bB.w};
                #pragma unroll
                for (int i = 0; i < 4; i++)
                    #pragma unroll
                    for (int j = 0; j < 8; j++) acc[i][j] += av[i] * bv[j];
            }
            float4 kcA = *(const float4*)&kcs[mA];
            float4 kcB = *(const float4*)&kcs[mB];
            float kcv[8] = {kcA.x, kcA.y, kcA.z, kcA.w, kcB.x, kcB.y, kcB.z, kcB.w};
            #pragma unroll
            for (int i = 0; i < 4; i++) {
                float mx = acc[i][0];
                #pragma unroll
                for (int j = 1; j < 8; j++) mx = fmaxf(mx, acc[i][j]);
                #pragma unroll
                for (int off = 16; off; off >>= 1)
                    mx = fmaxf(mx, __shfl_xor_sync(0xffffffffu, mx, off));
                float dg = diag[n0 + i];
                float qpv[8];
                float ds = 0.f;
                #pragma unroll
                for (int j = 0; j < 8; j++) {
                    qpv[j] = __expf(acc[i][j] - dg - mx) + EPSF;   // EPS outside exp for queries
                    ds += qpv[j] * kcv[j];
                }
                *(float4*)&kp[(n0 + i) * KPLD + mA] = make_float4(qpv[0], qpv[1], qpv[2], qpv[3]);
                *(float4*)&kp[(n0 + i) * KPLD + mB] = make_float4(qpv[4], qpv[5], qpv[6], qpv[7]);
                #pragma unroll
                for (int off = 16; off; off >>= 1)
                    ds += __shfl_xor_sync(0xffffffffu, ds, off);
                if (c == 0) dinv[n0 + i] = 1.0f / ds;
            }
        }
        __syncthreads();
        // out GEMM: out[n][e] = dinv[n] * sum_m qp[n][m] * ctx[m][e]
        {
            const int r0 = (tid >> 4) * 2;
            const int e0 = (tid & 15) * 4;
            float o0[4] = {0.f, 0.f, 0.f, 0.f};
            float o1[4] = {0.f, 0.f, 0.f, 0.f};
            #pragma unroll 4
            for (int mc = 0; mc < M_FEAT; mc += 8) {
                float4 qa0 = *(const float4*)&kp[r0 * KPLD + mc];
                float4 qa1 = *(const float4*)&kp[r0 * KPLD + mc + 4];
                float4 qb0 = *(const float4*)&kp[(r0 + 1) * KPLD + mc];
                float4 qb1 = *(const float4*)&kp[(r0 + 1) * KPLD + mc + 4];
                float qa[8] = {qa0.x, qa0.y, qa0.z, qa0.w, qa1.x, qa1.y, qa1.z, qa1.w};
                float qb[8] = {qb0.x, qb0.y, qb0.z, qb0.w, qb1.x, qb1.y, qb1.z, qb1.w};
                #pragma unroll
                for (int j = 0; j < 8; j++) {
                    float4 cv = *(const float4*)&ctx[(mc + j) * D_DIM + e0];
                    o0[0] += qa[j] * cv.x; o0[1] += qa[j] * cv.y;
                    o0[2] += qa[j] * cv.z; o0[3] += qa[j] * cv.w;
                    o1[0] += qb[j] * cv.x; o1[1] += qb[j] * cv.y;
                    o1[2] += qb[j] * cv.z; o1[3] += qb[j] * cv.w;
                }
            }
            float d0 = dinv[r0], d1 = dinv[r0 + 1];
            *(float4*)&og[(t * NT + r0) * D_DIM + e0] =
                make_float4(o0[0] * d0, o0[1] * d0, o0[2] * d0, o0[3] * d0);
            *(float4*)&og[(t * NT + r0 + 1) * D_DIM + e0] =
                make_float4(o1[0] * d1, o1[1] * d1, o1[2] * d1, o1[3] * d1);
        }
    }
}

extern "C" void kernel_launch(void* const* d_in, const int* in_sizes, int n_in,
                              void* d_out, int out_size)
{
    (void)n_in; (void)out_size;
    const float* q = (const float*)d_in[0];
    const float* k = (const float*)d_in[1];
    const float* v = (const float*)d_in[2];
    const float* P = (const float*)d_in[3];
    float* out = (float*)d_out;

    const int bh = in_sizes[0] / (N_TOK * D_DIM);   // 128

    cudaFuncSetAttribute(fastattn_kernel,
                         cudaFuncAttributeMaxDynamicSharedMemorySize, SMEM_BYTES);
    fastattn_kernel<<<bh, THREADS, SMEM_BYTES>>>(q, k, v, P, out);
}

// round 6
// speedup vs baseline: 1.0647x; 1.0638x over previous
#include <cuda_runtime.h>

// ---------------------------------------------------------------------------
// Performer (FAVOR+) linear attention, fully fused, fp32 SIMT with packed
// fma.rn.f32x2 (Blackwell) in all four GEMMs. One CTA per (b,h).
// Phase 1: context[m,e] = k'^T v and kcs[m] = colsum(k').
// Phase 2: q' rows -> D_inv -> out = (q' @ context) * D_inv.
// ratio = m^-0.5 cancels through D_inv and is dropped.
// ---------------------------------------------------------------------------

namespace {
constexpr int N_TOK  = 2048;
constexpr int D_DIM  = 64;
constexpr int M_FEAT = 256;
constexpr int NT     = 64;                 // rows per tile
constexpr int NTILES = N_TOK / NT;         // 32
constexpr int THREADS = 512;

constexpr int KPLD  = 260;                 // kp/qp row stride (floats): 16B-aligned, +4 pad
constexpr int KSTLD = 68;                  // Kst/Qst row stride (floats)

// smem layout (float offsets)
constexpr int OFF_P    = 0;                         // Pst[64][256]        16384
constexpr int OFF_KP   = OFF_P   + D_DIM * M_FEAT;  // kp/qp[64][260]      16640
constexpr int OFF_KST  = OFF_KP  + NT * KPLD;       // Kst/Qst[64][68]      4352
constexpr int OFF_X    = OFF_KST + D_DIM * KSTLD;   // Vs[64][64] | ctx[256][64] 16384
constexpr int OFF_KCS  = OFF_X   + M_FEAT * D_DIM;  // kcs[256]
constexpr int OFF_DIAG = OFF_KCS + M_FEAT;          // diag[64]
constexpr int OFF_DINV = OFF_DIAG + NT;             // dinv[64]
constexpr int SMEM_FLOATS = OFF_DINV + NT;          // 54144 floats
constexpr int SMEM_BYTES  = SMEM_FLOATS * 4;        // 216576 bytes

constexpr float NRM  = 0.35355339059327373f;        // 64^-0.25
constexpr float EPSF = 1e-4f;
}

// ---- packed fp32x2 helpers (sm_100a) ----
using ull = unsigned long long;

__device__ __forceinline__ ull dup2(float x) {
    ull r;
    asm("mov.b64 %0, {%1, %1};" : "=l"(r) : "f"(x));
    return r;
}
__device__ __forceinline__ void ffma2(ull& d, ull a, ull b) {
    asm("fma.rn.f32x2 %0, %1, %2, %0;" : "+l"(d) : "l"(a), "l"(b));
}
__device__ __forceinline__ float2 unpk(ull v) {
    float2 f;
    asm("mov.b64 {%0, %1}, %2;" : "=f"(f.x), "=f"(f.y) : "l"(v));
    return f;
}

__global__ __launch_bounds__(THREADS, 1)
void fastattn_kernel(const float* __restrict__ qg_,
                     const float* __restrict__ kg_,
                     const float* __restrict__ vg_,
                     const float* __restrict__ Pg,
                     float* __restrict__ outg_)
{
    extern __shared__ float sm[];
    float* Ps   = sm + OFF_P;     // [d][m] transposed projection
    float* kp   = sm + OFF_KP;    // k' / q' tile  [n][KPLD]
    float* Ks   = sm + OFF_KST;   // K/Q tile transposed, pre-scaled  [d][KSTLD]
    float* Vs   = sm + OFF_X;     // V tile [n][64]          (phase 1)
    float* ctx  = sm + OFF_X;     // context [m][64]         (phase 2, aliases Vs)
    float* kcs  = sm + OFF_KCS;   // column sums of k'
    float* diag = sm + OFF_DIAG;
    float* dinv = sm + OFF_DINV;

    const int tid = threadIdx.x;
    const int w   = tid >> 5;     // warp 0..15
    const int c   = tid & 31;     // lane
    const int bh  = blockIdx.x;

    const float* qg = qg_ + (size_t)bh * N_TOK * D_DIM;
    const float* kg = kg_ + (size_t)bh * N_TOK * D_DIM;
    const float* vg = vg_ + (size_t)bh * N_TOK * D_DIM;
    float*       og = outg_ + (size_t)bh * N_TOK * D_DIM;

    // ---- load P transposed into smem (once) ----
    for (int i = tid; i < M_FEAT * D_DIM / 4; i += THREADS) {
        int m  = i >> 4;          // 16 float4 per 64-float row
        int d4 = (i & 15) * 4;
        float4 pv = ((const float4*)Pg)[i];
        Ps[(d4 + 0) * M_FEAT + m] = pv.x;
        Ps[(d4 + 1) * M_FEAT + m] = pv.y;
        Ps[(d4 + 2) * M_FEAT + m] = pv.z;
        Ps[(d4 + 3) * M_FEAT + m] = pv.w;
    }

    // ---- phase 1: context & kcs ----
    // cacc2[j2][e]: m-pair j2 in {(mA,mA+1),(mA+2,mA+3),(mB,mB+1),(mB+2,mB+3)},
    //               e in {4w..4w+3}; each ull packs (m_lo, m_hi) for one e.
    ull cacc2[4][4];
    #pragma unroll
    for (int j = 0; j < 4; j++)
        #pragma unroll
        for (int e = 0; e < 4; e++) cacc2[j][e] = 0ull;
    float kcsr = 0.f;             // threads < 256: column tid of kcs

    for (int t = 0; t < NTILES; t++) {
        const float* kt = kg + t * NT * D_DIM;
        const float* vt = vg + t * NT * D_DIM;
        __syncthreads();          // previous tile fully consumed
        // load K (transpose + scale) and V
        #pragma unroll
        for (int r = 0; r < 2; r++) {
            int i  = tid + r * THREADS;          // 0..1023
            int n  = i >> 4;
            int d4 = (i & 15) * 4;
            float4 kv = ((const float4*)kt)[i];
            Ks[(d4 + 0) * KSTLD + n] = kv.x * NRM;
            Ks[(d4 + 1) * KSTLD + n] = kv.y * NRM;
            Ks[(d4 + 2) * KSTLD + n] = kv.z * NRM;
            Ks[(d4 + 3) * KSTLD + n] = kv.w * NRM;
            ((float4*)Vs)[i] = ((const float4*)vt)[i];
        }
        __syncthreads();
        if (tid < NT) {           // diag[n] = 0.5 * sum_d (scaled)^2
            float s = 0.f;
            #pragma unroll 8
            for (int d = 0; d < D_DIM; d++) { float x = Ks[d * KSTLD + tid]; s += x * x; }
            diag[tid] = 0.5f * s;
        }
        __syncthreads();
        // kdash GEMM (64x256, K=64), fused exp -> kp.  Packed over m.
        {
            ull acc2[4][4];       // [row i][m-pair j2]
            #pragma unroll
            for (int i = 0; i < 4; i++)
                #pragma unroll
                for (int j = 0; j < 4; j++) acc2[i][j] = 0ull;
            const int n0 = w * 4, mA = c * 4, mB = 128 + c * 4;
            #pragma unroll 4
            for (int d = 0; d < D_DIM; d++) {
                float4 a = *(const float4*)&Ks[d * KSTLD + n0];
                ulonglong2 bA = *(const ulonglong2*)&Ps[d * M_FEAT + mA];
                ulonglong2 bB = *(const ulonglong2*)&Ps[d * M_FEAT + mB];
                ull pa[4] = {dup2(a.x), dup2(a.y), dup2(a.z), dup2(a.w)};
                #pragma unroll
                for (int i = 0; i < 4; i++) {
                    ffma2(acc2[i][0], pa[i], bA.x);
                    ffma2(acc2[i][1], pa[i], bA.y);
                    ffma2(acc2[i][2], pa[i], bB.x);
                    ffma2(acc2[i][3], pa[i], bB.y);
                }
            }
            #pragma unroll
            for (int i = 0; i < 4; i++) {
                float dg = diag[n0 + i];
                float2 a0 = unpk(acc2[i][0]), a1 = unpk(acc2[i][1]);
                float2 a2 = unpk(acc2[i][2]), a3 = unpk(acc2[i][3]);
                float4 e0, e1;
                e0.x = __expf(a0.x - dg + EPSF);
                e0.y = __expf(a0.y - dg + EPSF);
                e0.z = __expf(a1.x - dg + EPSF);
                e0.w = __expf(a1.y - dg + EPSF);
                e1.x = __expf(a2.x - dg + EPSF);
                e1.y = __expf(a2.y - dg + EPSF);
                e1.z = __expf(a3.x - dg + EPSF);
                e1.w = __expf(a3.y - dg + EPSF);
                *(float4*)&kp[(n0 + i) * KPLD + mA] = e0;
                *(float4*)&kp[(n0 + i) * KPLD + mB] = e1;
            }
        }
        __syncthreads();
        // kcs partial sums (thread t owns column t)
        if (tid < M_FEAT) {
            float s = 0.f;
            #pragma unroll 8
            for (int n = 0; n < NT; n++) s += kp[n * KPLD + tid];
            kcsr += s;
        }
        // ctx GEMM: ctx[m][e] += kp[n][m] * Vs[n][e].  Packed over m, dup V (warp-uniform).
        {
            const int mA = c * 4, mB = 128 + c * 4, e0 = w * 4;
            #pragma unroll 4
            for (int n = 0; n < NT; n++) {
                ulonglong2 kA = *(const ulonglong2*)&kp[n * KPLD + mA];
                ulonglong2 kB = *(const ulonglong2*)&kp[n * KPLD + mB];
                float4 vv = *(const float4*)&Vs[n * D_DIM + e0];
                ull ev[4] = {dup2(vv.x), dup2(vv.y), dup2(vv.z), dup2(vv.w)};
                #pragma unroll
                for (int e = 0; e < 4; e++) {
                    ffma2(cacc2[0][e], kA.x, ev[e]);
                    ffma2(cacc2[1][e], kA.y, ev[e]);
                    ffma2(cacc2[2][e], kB.x, ev[e]);
                    ffma2(cacc2[3][e], kB.y, ev[e]);
                }
            }
        }
    }
    __syncthreads();              // last tile done; Vs dead -> ctx can be written
    {
        const int mA = c * 4, mB = 128 + c * 4, e0 = w * 4;
        // cacc2[j2][e] packs (m_lo, m_hi) for column e0+e.
        #pragma unroll
        for (int j = 0; j < 2; j++) {     // pairs within mA block
            float2 u0 = unpk(cacc2[j][0]), u1 = unpk(cacc2[j][1]);
            float2 u2 = unpk(cacc2[j][2]), u3 = unpk(cacc2[j][3]);
            *(float4*)&ctx[(mA + 2*j    ) * D_DIM + e0] = make_float4(u0.x, u1.x, u2.x, u3.x);
            *(float4*)&ctx[(mA + 2*j + 1) * D_DIM + e0] = make_float4(u0.y, u1.y, u2.y, u3.y);
        }
        #pragma unroll
        for (int j = 0; j < 2; j++) {     // pairs within mB block
            float2 u0 = unpk(cacc2[2+j][0]), u1 = unpk(cacc2[2+j][1]);
            float2 u2 = unpk(cacc2[2+j][2]), u3 = unpk(cacc2[2+j][3]);
            *(float4*)&ctx[(mB + 2*j    ) * D_DIM + e0] = make_float4(u0.x, u1.x, u2.x, u3.x);
            *(float4*)&ctx[(mB + 2*j + 1) * D_DIM + e0] = make_float4(u0.y, u1.y, u2.y, u3.y);
        }
        if (tid < M_FEAT) kcs[tid] = kcsr;
    }

    // ---- phase 2: q', D_inv, out ----
    for (int t = 0; t < NTILES; t++) {
        const float* qt = qg + t * NT * D_DIM;
        __syncthreads();          // ctx/kcs visible; previous out GEMM done with qp
        #pragma unroll
        for (int r = 0; r < 2; r++) {
            int i  = tid + r * THREADS;
            int n  = i >> 4;
            int d4 = (i & 15) * 4;
            float4 qv = ((const float4*)qt)[i];
            Ks[(d4 + 0) * KSTLD + n] = qv.x * NRM;
            Ks[(d4 + 1) * KSTLD + n] = qv.y * NRM;
            Ks[(d4 + 2) * KSTLD + n] = qv.z * NRM;
            Ks[(d4 + 3) * KSTLD + n] = qv.w * NRM;
        }
        __syncthreads();
        if (tid < NT) {
            float s = 0.f;
            #pragma unroll 8
            for (int d = 0; d < D_DIM; d++) { float x = Ks[d * KSTLD + tid]; s += x * x; }
            diag[tid] = 0.5f * s;
        }
        __syncthreads();
        // qdash GEMM (packed) + rowmax + exp + denom
        {
            ull acc2[4][4];
            #pragma unroll
            for (int i = 0; i < 4; i++)
                #pragma unroll
                for (int j = 0; j < 4; j++) acc2[i][j] = 0ull;
            const int n0 = w * 4, mA = c * 4, mB = 128 + c * 4;
            #pragma unroll 4
            for (int d = 0; d < D_DIM; d++) {
                float4 a = *(const float4*)&Ks[d * KSTLD + n0];
                ulonglong2 bA = *(const ulonglong2*)&Ps[d * M_FEAT + mA];
                ulonglong2 bB = *(const ulonglong2*)&Ps[d * M_FEAT + mB];
                ull pa[4] = {dup2(a.x), dup2(a.y), dup2(a.z), dup2(a.w)};
                #pragma unroll
                for (int i = 0; i < 4; i++) {
                    ffma2(acc2[i][0], pa[i], bA.x);
                    ffma2(acc2[i][1], pa[i], bA.y);
                    ffma2(acc2[i][2], pa[i], bB.x);
                    ffma2(acc2[i][3], pa[i], bB.y);
                }
            }
            float4 kcA = *(const float4*)&kcs[mA];
            float4 kcB = *(const float4*)&kcs[mB];
            float kcv[8] = {kcA.x, kcA.y, kcA.z, kcA.w, kcB.x, kcB.y, kcB.z, kcB.w};
            #pragma unroll
            for (int i = 0; i < 4; i++) {
                float2 a0 = unpk(acc2[i][0]), a1 = unpk(acc2[i][1]);
                float2 a2 = unpk(acc2[i][2]), a3 = unpk(acc2[i][3]);
                float acc[8] = {a0.x, a0.y, a1.x, a1.y, a2.x, a2.y, a3.x, a3.y};
                float mx = acc[0];
                #pragma unroll
                for (int j = 1; j < 8; j++) mx = fmaxf(mx, acc[j]);
                #pragma unroll
                for (int off = 16; off; off >>= 1)
                    mx = fmaxf(mx, __shfl_xor_sync(0xffffffffu, mx, off));
                float dg = diag[n0 + i];
                float qpv[8];
                float ds = 0.f;
                #pragma unroll
                for (int j = 0; j < 8; j++) {
                    qpv[j] = __expf(acc[j] - dg - mx) + EPSF;   // EPS outside exp for queries
                    ds += qpv[j] * kcv[j];
                }
                *(float4*)&kp[(n0 + i) * KPLD + mA] = make_float4(qpv[0], qpv[1], qpv[2], qpv[3]);
                *(float4*)&kp[(n0 + i) * KPLD + mB] = make_float4(qpv[4], qpv[5], qpv[6], qpv[7]);
                #pragma unroll
                for (int off = 16; off; off >>= 1)
                    ds += __shfl_xor_sync(0xffffffffu, ds, off);
                if (c == 0) dinv[n0 + i] = 1.0f / ds;
            }
        }
        __syncthreads();
        // out GEMM: out[n][e] = dinv[n] * sum_m qp[n][m] * ctx[m][e].
        // Packed over e (ctx rows contiguous, 16B aligned), dup q scalar.
        {
            const int r0 = (tid >> 4) * 2;
            const int e0 = (tid & 15) * 4;
            ull o2[2][2] = {{0ull, 0ull}, {0ull, 0ull}};
            #pragma unroll 2
            for (int mc = 0; mc < M_FEAT; mc += 8) {
                float4 qa0 = *(const float4*)&kp[r0 * KPLD + mc];
                float4 qa1 = *(const float4*)&kp[r0 * KPLD + mc + 4];
                float4 qb0 = *(const float4*)&kp[(r0 + 1) * KPLD + mc];
                float4 qb1 = *(const float4*)&kp[(r0 + 1) * KPLD + mc + 4];
                float qa[8] = {qa0.x, qa0.y, qa0.z, qa0.w, qa1.x, qa1.y, qa1.z, qa1.w};
                float qb[8] = {qb0.x, qb0.y, qb0.z, qb0.w, qb1.x, qb1.y, qb1.z, qb1.w};
                #pragma unroll
                for (int j = 0; j < 8; j++) {
                    ulonglong2 cv = *(const ulonglong2*)&ctx[(mc + j) * D_DIM + e0];
                    ull da = dup2(qa[j]);
                    ull db = dup2(qb[j]);
                    ffma2(o2[0][0], da, cv.x);
                    ffma2(o2[0][1], da, cv.y);
                    ffma2(o2[1][0], db, cv.x);
                    ffma2(o2[1][1], db, cv.y);
                }
            }
            float d0 = dinv[r0], d1 = dinv[r0 + 1];
            float2 p00 = unpk(o2[0][0]), p01 = unpk(o2[0][1]);
            float2 p10 = unpk(o2[1][0]), p11 = unpk(o2[1][1]);
            *(float4*)&og[(t * NT + r0) * D_DIM + e0] =
                make_float4(p00.x * d0, p00.y * d0, p01.x * d0, p01.y * d0);
            *(float4*)&og[(t * NT + r0 + 1) * D_DIM + e0] =
                make_float4(p10.x * d1, p10.y * d1, p11.x * d1, p11.y * d1);
        }
    }
}

extern "C" void kernel_launch(void* const* d_in, const int* in_sizes, int n_in,
                              void* d_out, int out_size)
{
    (void)n_in; (void)out_size;
    const float* q = (const float*)d_in[0];
    const float* k = (const float*)d_in[1];
    const float* v = (const float*)d_in[2];
    const float* P = (const float*)d_in[3];
    float* out = (float*)d_out;

    const int bh = in_sizes[0] / (N_TOK * D_DIM);   // 128

    cudaFuncSetAttribute(fastattn_kernel,
                         cudaFuncAttributeMaxDynamicSharedMemorySize, SMEM_BYTES);
    fastattn_kernel<<<bh, THREADS, SMEM_BYTES>>>(q, k, v, P, out);
}

// round 7
// speedup vs baseline: 1.2193x; 1.1452x over previous
#include <cuda_runtime.h>

// ---------------------------------------------------------------------------
// Performer (FAVOR+) linear attention, fully fused, fp32 with packed
// fma.rn.f32x2. Restructured so every GEMM has a warp-uniform (broadcast)
// smem operand -> smem crossbar traffic cut ~2x vs R5; fma-issue bound.
// One CTA per (b,h). ratio = m^-0.5 cancels through D_inv and is dropped.
// NRM is folded into Ps; diag uses 0.5*NRM^2 = 1/16.
// ---------------------------------------------------------------------------

namespace {
constexpr int N_TOK  = 2048;
constexpr int D_DIM  = 64;
constexpr int M_FEAT = 256;
constexpr int NT     = 64;                 // rows per tile
constexpr int NTILES = N_TOK / NT;         // 32
constexpr int THREADS = 512;

constexpr int PSLD = 260;                  // Ps row stride (floats)
constexpr int KSLD = 68;                   // Ks row stride [n][d] layout
constexpr int KPLD = 260;                  // kp row stride

// smem layout (float offsets)
constexpr int OFF_P    = 0;                          // Ps[64][260]   16640
constexpr int OFF_KP   = OFF_P   + D_DIM * PSLD;     // kp[64][260]   16640
constexpr int OFF_KS   = OFF_KP  + NT * KPLD;        // Ks[64][68]     4352 (also pbuf[4096])
constexpr int OFF_X    = OFF_KS  + NT * KSLD;        // Vs[64][64]|ctx[256][64] 16384
constexpr int OFF_KCS  = OFF_X   + M_FEAT * D_DIM;   // kcs[256]
constexpr int OFF_DIAG = OFF_KCS + M_FEAT;           // diag[64]
constexpr int OFF_DINV = OFF_DIAG + NT;              // dinv[64]
constexpr int OFF_HM   = OFF_DINV + NT;              // hm[64][2]
constexpr int OFF_HD   = OFF_HM + 2 * NT;            // hd[64][2]
constexpr int SMEM_FLOATS = OFF_HD + 2 * NT;         // 54656
constexpr int SMEM_BYTES  = SMEM_FLOATS * 4;         // 218624

constexpr float NRM   = 0.35355339059327373f;        // 64^-0.25
constexpr float DIAGC = 0.0625f;                     // 0.5 * NRM^2
constexpr float EPSF  = 1e-4f;
}

// ---- packed fp32x2 helpers (sm_100a) ----
using ull = unsigned long long;

__device__ __forceinline__ ull dup2(float x) {
    ull r;
    asm("mov.b64 %0, {%1, %1};" : "=l"(r) : "f"(x));
    return r;
}
__device__ __forceinline__ void ffma2(ull& d, ull a, ull b) {
    asm("fma.rn.f32x2 %0, %1, %2, %0;" : "+l"(d) : "l"(a), "l"(b));
}
__device__ __forceinline__ float2 unpk(ull v) {
    float2 f;
    asm("mov.b64 {%0, %1}, %2;" : "=f"(f.x), "=f"(f.y) : "l"(v));
    return f;
}

__global__ __launch_bounds__(THREADS, 1)
void fastattn_kernel(const float* __restrict__ qg_,
                     const float* __restrict__ kg_,
                     const float* __restrict__ vg_,
                     const float* __restrict__ Pg,
                     float* __restrict__ outg_)
{
    extern __shared__ float sm[];
    float* Ps   = sm + OFF_P;     // [d][PSLD], pre-scaled by NRM
    float* kp   = sm + OFF_KP;    // k'/q' tile [n][KPLD]
    float* Ks   = sm + OFF_KS;    // K/Q tile [n][KSLD] raw; later pbuf[64][64]
    float* pbuf = sm + OFF_KS;
    float* Vs   = sm + OFF_X;     // V tile [n][64]  (phase 1)
    float* ctx  = sm + OFF_X;     // context [m][64] (phase 2, aliases Vs)
    float* kcs  = sm + OFF_KCS;
    float* diag = sm + OFF_DIAG;
    float* dinv = sm + OFF_DINV;
    float* hm   = sm + OFF_HM;    // per-row half maxima  [64][2]
    float* hd   = sm + OFF_HD;    // per-row half denoms  [64][2]

    const int tid = threadIdx.x;
    const int w   = tid >> 5;
    const int c   = tid & 31;
    const int bh  = blockIdx.x;

    const float* qg = qg_ + (size_t)bh * N_TOK * D_DIM;
    const float* kg = kg_ + (size_t)bh * N_TOK * D_DIM;
    const float* vg = vg_ + (size_t)bh * N_TOK * D_DIM;
    float*       og = outg_ + (size_t)bh * N_TOK * D_DIM;

    // warp roles for projection GEMMs: 8-row group x m-half
    const int nh   = w >> 1;            // 0..7
    const int half = w & 1;             // 0..1
    const int r0   = nh * 8;
    const int mb   = half * 128 + c * 4;

    // warp roles for ctx GEMM: m-half x 8-e group
    const int chalf = w & 1;
    const int e0c   = (w >> 1) * 8;
    const int mbc   = chalf * 128 + c * 4;

    // thread roles for out GEMM: 2 m-groups x (16 n-quads x 16 e-quads)
    const int g   = tid >> 8;           // m-half group
    const int gt  = tid & 255;
    const int et  = gt & 15;
    const int ntq = gt >> 4;
    const int ro  = ntq * 4;
    const int e0o = et * 4;
    const int mbo = g * 128;

    // ---- load Ps = NRM * P, transposed [d][m] ----
    for (int i = tid; i < M_FEAT * D_DIM / 4; i += THREADS) {
        int m  = i >> 4;
        int d4 = (i & 15) * 4;
        float4 pv = ((const float4*)Pg)[i];
        Ps[(d4 + 0) * PSLD + m] = pv.x * NRM;
        Ps[(d4 + 1) * PSLD + m] = pv.y * NRM;
        Ps[(d4 + 2) * PSLD + m] = pv.z * NRM;
        Ps[(d4 + 3) * PSLD + m] = pv.w * NRM;
    }

    // ---- phase 1: context & kcs ----
    ull cacc2[2][8];                    // [m-pair][e] for ctx GEMM
    #pragma unroll
    for (int p = 0; p < 2; p++)
        #pragma unroll
        for (int e = 0; e < 8; e++) cacc2[p][e] = 0ull;
    float kcsr = 0.f;

    for (int t = 0; t < NTILES; t++) {
        const float* kt = kg + t * NT * D_DIM;
        const float* vt = vg + t * NT * D_DIM;
        __syncthreads();
        // stage K (row-major copy) and V
        #pragma unroll
        for (int r = 0; r < 2; r++) {
            int i  = tid + r * THREADS;
            int n  = i >> 4;
            int d4 = (i & 15) * 4;
            *(float4*)&Ks[n * KSLD + d4] = ((const float4*)kt)[i];
            ((float4*)Vs)[i] = ((const float4*)vt)[i];
        }
        __syncthreads();
        if (tid < NT) {                 // diag[n] = (sum k^2)/16
            float s = 0.f;
            #pragma unroll
            for (int d4 = 0; d4 < D_DIM; d4 += 4) {
                float4 x = *(const float4*)&Ks[tid * KSLD + d4];
                s += x.x * x.x + x.y * x.y + x.z * x.z + x.w * x.w;
            }
            diag[tid] = s * DIAGC;
        }
        __syncthreads();
        // kdash GEMM: 8 rows x 4 m per thread, fused exp -> kp
        {
            ull acc2[8][2];
            #pragma unroll
            for (int i = 0; i < 8; i++) { acc2[i][0] = 0ull; acc2[i][1] = 0ull; }
            for (int dc = 0; dc < D_DIM; dc += 4) {
                float4 a4[8];
                #pragma unroll
                for (int i = 0; i < 8; i++)
                    a4[i] = *(const float4*)&Ks[(r0 + i) * KSLD + dc];
                #pragma unroll
                for (int j = 0; j < 4; j++) {
                    ulonglong2 bb = *(const ulonglong2*)&Ps[(dc + j) * PSLD + mb];
                    #pragma unroll
                    for (int i = 0; i < 8; i++) {
                        const float* af = &a4[i].x;
                        ull ad = dup2(af[j]);
                        ffma2(acc2[i][0], ad, bb.x);
                        ffma2(acc2[i][1], ad, bb.y);
                    }
                }
            }
            #pragma unroll
            for (int i = 0; i < 8; i++) {
                float dg = diag[r0 + i];
                float2 u0 = unpk(acc2[i][0]);
                float2 u1 = unpk(acc2[i][1]);
                float4 e;
                e.x = __expf(u0.x - dg + EPSF);
                e.y = __expf(u0.y - dg + EPSF);
                e.z = __expf(u1.x - dg + EPSF);
                e.w = __expf(u1.y - dg + EPSF);
                *(float4*)&kp[(r0 + i) * KPLD + mb] = e;
            }
        }
        __syncthreads();
        // kcs partials
        if (tid < M_FEAT) {
            float s = 0.f;
            #pragma unroll 8
            for (int n = 0; n < NT; n++) s += kp[n * KPLD + tid];
            kcsr += s;
        }
        // ctx GEMM: ctx[m][e] += kp[n][m] * V[n][e]; V broadcast
        {
            #pragma unroll 4
            for (int n = 0; n < NT; n++) {
                ulonglong2 ka = *(const ulonglong2*)&kp[n * KPLD + mbc];
                float4 v0 = *(const float4*)&Vs[n * D_DIM + e0c];
                float4 v1 = *(const float4*)&Vs[n * D_DIM + e0c + 4];
                const float vv[8] = {v0.x, v0.y, v0.z, v0.w, v1.x, v1.y, v1.z, v1.w};
                #pragma unroll
                for (int e = 0; e < 8; e++) {
                    ull vd = dup2(vv[e]);
                    ffma2(cacc2[0][e], ka.x, vd);
                    ffma2(cacc2[1][e], ka.y, vd);
                }
            }
        }
    }
    __syncthreads();                    // Vs dead -> write ctx
    {
        #pragma unroll
        for (int p = 0; p < 2; p++) {
            float2 u[8];
            #pragma unroll
            for (int e = 0; e < 8; e++) u[e] = unpk(cacc2[p][e]);
            int m0 = mbc + 2 * p;
            *(float4*)&ctx[m0 * D_DIM + e0c]     = make_float4(u[0].x, u[1].x, u[2].x, u[3].x);
            *(float4*)&ctx[m0 * D_DIM + e0c + 4] = make_float4(u[4].x, u[5].x, u[6].x, u[7].x);
            *(float4*)&ctx[(m0 + 1) * D_DIM + e0c]     = make_float4(u[0].y, u[1].y, u[2].y, u[3].y);
            *(float4*)&ctx[(m0 + 1) * D_DIM + e0c + 4] = make_float4(u[4].y, u[5].y, u[6].y, u[7].y);
        }
        if (tid < M_FEAT) kcs[tid] = kcsr;
    }

    // ---- phase 2: q', D_inv, out ----
    for (int t = 0; t < NTILES; t++) {
        const float* qt = qg + t * NT * D_DIM;
        __syncthreads();                // prev combine done with pbuf/kp; ctx ready
        #pragma unroll
        for (int r = 0; r < 2; r++) {
            int i  = tid + r * THREADS;
            int n  = i >> 4;
            int d4 = (i & 15) * 4;
            *(float4*)&Ks[n * KSLD + d4] = ((const float4*)qt)[i];
        }
        __syncthreads();
        if (tid < NT) {
            float s = 0.f;
            #pragma unroll
            for (int d4 = 0; d4 < D_DIM; d4 += 4) {
                float4 x = *(const float4*)&Ks[tid * KSLD + d4];
                s += x.x * x.x + x.y * x.y + x.z * x.z + x.w * x.w;
            }
            diag[tid] = s * DIAGC;
        }
        __syncthreads();
        // qdash GEMM + two-stage (half-warp) max/denom reduction
        {
            ull acc2[8][2];
            #pragma unroll
            for (int i = 0; i < 8; i++) { acc2[i][0] = 0ull; acc2[i][1] = 0ull; }
            for (int dc = 0; dc < D_DIM; dc += 4) {
                float4 a4[8];
                #pragma unroll
                for (int i = 0; i < 8; i++)
                    a4[i] = *(const float4*)&Ks[(r0 + i) * KSLD + dc];
                #pragma unroll
                for (int j = 0; j < 4; j++) {
                    ulonglong2 bb = *(const ulonglong2*)&Ps[(dc + j) * PSLD + mb];
                    #pragma unroll
                    for (int i = 0; i < 8; i++) {
                        const float* af = &a4[i].x;
                        ull ad = dup2(af[j]);
                        ffma2(acc2[i][0], ad, bb.x);
                        ffma2(acc2[i][1], ad, bb.y);
                    }
                }
            }
            // stage 1: per-row half-max
            #pragma unroll
            for (int i = 0; i < 8; i++) {
                float2 u0 = unpk(acc2[i][0]);
                float2 u1 = unpk(acc2[i][1]);
                float lm = fmaxf(fmaxf(u0.x, u0.y), fmaxf(u1.x, u1.y));
                #pragma unroll
                for (int off = 16; off; off >>= 1)
                    lm = fmaxf(lm, __shfl_xor_sync(0xffffffffu, lm, off));
                if (c == 0) hm[(r0 + i) * 2 + half] = lm;
            }
            __syncthreads();
            // stage 2: qpv + half-denominators
            float4 kc = *(const float4*)&kcs[mb];
            #pragma unroll
            for (int i = 0; i < 8; i++) {
                int r = r0 + i;
                float mx = fmaxf(hm[r * 2], hm[r * 2 + 1]);
                float dg = diag[r];
                float2 u0 = unpk(acc2[i][0]);
                float2 u1 = unpk(acc2[i][1]);
                float4 qv;
                qv.x = __expf(u0.x - dg - mx) + EPSF;
                qv.y = __expf(u0.y - dg - mx) + EPSF;
                qv.z = __expf(u1.x - dg - mx) + EPSF;
                qv.w = __expf(u1.y - dg - mx) + EPSF;
                *(float4*)&kp[r * KPLD + mb] = qv;
                float ds = qv.x * kc.x + qv.y * kc.y + qv.z * kc.z + qv.w * kc.w;
                #pragma unroll
                for (int off = 16; off; off >>= 1)
                    ds += __shfl_xor_sync(0xffffffffu, ds, off);
                if (c == 0) hd[r * 2 + half] = ds;
            }
        }
        __syncthreads();
        if (tid < NT) dinv[tid] = 1.0f / (hd[tid * 2] + hd[tid * 2 + 1]);
        // out GEMM: split m-reduction, 4 rows x 4 e per thread
        {
            ull o2[4][2];
            #pragma unroll
            for (int i = 0; i < 4; i++) { o2[i][0] = 0ull; o2[i][1] = 0ull; }
            for (int mc = 0; mc < 128; mc += 8) {
                float4 qv[4][2];
                #pragma unroll
                for (int i = 0; i < 4; i++) {
                    qv[i][0] = *(const float4*)&kp[(ro + i) * KPLD + mbo + mc];
                    qv[i][1] = *(const float4*)&kp[(ro + i) * KPLD + mbo + mc + 4];
                }
                #pragma unroll
                for (int j = 0; j < 8; j++) {
                    ulonglong2 cv = *(const ulonglong2*)&ctx[(mbo + mc + j) * D_DIM + e0o];
                    #pragma unroll
                    for (int i = 0; i < 4; i++) {
                        const float* qf = &qv[i][j >> 2].x;
                        ull qd = dup2(qf[j & 3]);
                        ffma2(o2[i][0], qd, cv.x);
                        ffma2(o2[i][1], qd, cv.y);
                    }
                }
            }
            if (g == 1) {               // store partials (Ks region is dead)
                #pragma unroll
                for (int i = 0; i < 4; i++) {
                    float2 p0 = unpk(o2[i][0]);
                    float2 p1 = unpk(o2[i][1]);
                    *(float4*)&pbuf[(ro + i) * 64 + e0o] =
                        make_float4(p0.x, p0.y, p1.x, p1.y);
                }
            }
            __syncthreads();
            if (g == 0) {               // combine + scale + store
                #pragma unroll
                for (int i = 0; i < 4; i++) {
                    int r = ro + i;
                    float4 pb = *(const float4*)&pbuf[r * 64 + e0o];
                    float2 p0 = unpk(o2[i][0]);
                    float2 p1 = unpk(o2[i][1]);
                    float dv = dinv[r];
                    *(float4*)&og[(t * NT + r) * D_DIM + e0o] =
                        make_float4((p0.x + pb.x) * dv, (p0.y + pb.y) * dv,
                                    (p1.x + pb.z) * dv, (p1.y + pb.w) * dv);
                }
            }
        }
    }
}

extern "C" void kernel_launch(void* const* d_in, const int* in_sizes, int n_in,
                              void* d_out, int out_size)
{
    (void)n_in; (void)out_size;
    const float* q = (const float*)d_in[0];
    const float* k = (const float*)d_in[1];
    const float* v = (const float*)d_in[2];
    const float* P = (const float*)d_in[3];
    float* out = (float*)d_out;

    const int bh = in_sizes[0] / (N_TOK * D_DIM);   // 128

    cudaFuncSetAttribute(fastattn_kernel,
                         cudaFuncAttributeMaxDynamicSharedMemorySize, SMEM_BYTES);
    fastattn_kernel<<<bh, THREADS, SMEM_BYTES>>>(q, k, v, P, out);
}